// round 15
// baseline (speedup 1.0000x reference)
#include <cuda_runtime.h>
#include <cuda_fp16.h>
#include <stdint.h>
#include <math.h>

// B=32, N=64, ATTR=4, STATE=8, REL=4, GDIM=32, NF=128, pstep=2
#define NNODES 2048

// ---------------- scratch (static device memory) ----------------
__device__ __half g_Eh[2048 * 64 * 128];   // E, [bi][j][f] fp16 (32 MB)
__device__ float g_obj[2048 * 128];
__device__ float g_u[2048 * 128];
__device__ float g_vt[32 * 128 * 64];      // [b][k][n]
__device__ float g_R[2048 * 128];
__device__ float g_S[2048 * 128];
__device__ float g_agg[2048 * 128];
__device__ __half g_w1h[128 * 128];        // re_w1 [f][k] fp16
__device__ __half g_wrh[128 * 128];        // rp_w rel-block [f][k] fp16

#define LDSM_X4(r, addr)                                                      \
    asm volatile("ldmatrix.sync.aligned.m8n8.x4.shared.b16 {%0,%1,%2,%3}, [%4];" \
                 : "=r"((r)[0]), "=r"((r)[1]), "=r"((r)[2]), "=r"((r)[3])     \
                 : "r"(addr))

#define MMA_F16(d, a, b0v, b1v)                                               \
    asm volatile(                                                             \
        "mma.sync.aligned.m16n8k16.row.col.f32.f16.f16.f32 "                  \
        "{%0,%1,%2,%3}, {%4,%5,%6,%7}, {%8,%9}, {%0,%1,%2,%3};"               \
        : "+f"((d)[0]), "+f"((d)[1]), "+f"((d)[2]), "+f"((d)[3])              \
        : "r"((a)[0]), "r"((a)[1]), "r"((a)[2]), "r"((a)[3]),                 \
          "r"(b0v), "r"(b1v))

// ---------------- fused prep + node_pre + obj_encode + rs(step0): 8 nodes/block ----------------
__global__ __launch_bounds__(128) void encode_all(const float* __restrict__ attrs,
                                                  const float* __restrict__ states,
                                                  const float* __restrict__ re_w0,
                                                  const float* __restrict__ re_b0,
                                                  const float* __restrict__ oe_w0,
                                                  const float* __restrict__ oe_b0,
                                                  const float* __restrict__ oe_w1,
                                                  const float* __restrict__ oe_b1,
                                                  const float* __restrict__ re_w1,
                                                  const float* __restrict__ rp_w,
                                                  const float* __restrict__ rp_b) {
    // ---- folded prep: one weight element per thread (256 blocks x 128 = 32768) ----
    {
        int gidx = blockIdx.x * 128 + threadIdx.x;
        if (gidx < 16384) {
            g_w1h[gidx] = __float2half_rn(re_w1[gidx]);
        } else {
            int i = gidx - 16384;
            int f = i >> 7, k = i & 127;
            g_wrh[i] = __float2half_rn(rp_w[f * 384 + k]);
        }
    }
    __shared__ float sa[8][4];
    __shared__ float ssm[8][8];
    __shared__ float Hs1[8][128];
    __shared__ float Os[8][128];
    int base = blockIdx.x * 8;
    int f = threadIdx.x;
    if (f < 32) {
        int n = f >> 2, c = f & 3;
        sa[n][c] = attrs[(base + n) * 4 + c];
    } else if (f < 96) {
        int q = f - 32;
        int n = q >> 3, c = q & 7;
        ssm[n][c] = states[(base + n) * 8 + c];
    }
    __syncthreads();
    {
        const float* w = re_w0 + f * 20;
        float ws[8], wr4[4], ws4[4];
#pragma unroll
        for (int c = 0; c < 8; c++) ws[c] = w[4 + c];
#pragma unroll
        for (int c = 0; c < 4; c++) { wr4[c] = w[12 + c]; ws4[c] = w[16 + c]; }
        float b0 = re_b0[f];
        int b = base >> 6;
#pragma unroll
        for (int n = 0; n < 8; n++) {
            float u = b0, v = 0.f;
#pragma unroll
            for (int c = 0; c < 8; c++) {
                u += ws[c] * ssm[n][c];
                v -= ws[c] * ssm[n][c];
            }
#pragma unroll
            for (int c = 0; c < 4; c++) {
                u += wr4[c] * sa[n][c];
                v += ws4[c] * sa[n][c];
            }
            int node = base + n;
            g_u[node * 128 + f] = u;
            g_vt[(b * 128 + f) * 64 + (node & 63)] = v;
        }
    }
    {
        float w0r[12];
#pragma unroll
        for (int c = 0; c < 12; c++) w0r[c] = oe_w0[f * 12 + c];
        float b0 = oe_b0[f];
#pragma unroll
        for (int n = 0; n < 8; n++) {
            float h = b0;
#pragma unroll
            for (int c = 0; c < 4; c++) h += w0r[c] * sa[n][c];
#pragma unroll
            for (int c = 0; c < 8; c++) h += w0r[4 + c] * ssm[n][c];
            Hs1[n][f] = fmaxf(h, 0.f);
        }
    }
    __syncthreads();
    {
        float acc[8] = {0, 0, 0, 0, 0, 0, 0, 0};
#pragma unroll 4
        for (int k = 0; k < 128; k += 4) {
            float4 w = *(const float4*)&oe_w1[f * 128 + k];
#pragma unroll
            for (int n = 0; n < 8; n++) {
                float4 x = *(const float4*)&Hs1[n][k];
                acc[n] += w.x * x.x + w.y * x.y + w.z * x.z + w.w * x.w;
            }
        }
        float b1 = oe_b1[f];
#pragma unroll
        for (int n = 0; n < 8; n++) {
            float o = fmaxf(acc[n] + b1, 0.f);
            Os[n][f] = o;
            g_obj[(base + n) * 128 + f] = o;
        }
    }
    __syncthreads();
    {
        float r[8] = {0, 0, 0, 0, 0, 0, 0, 0};
        float s[8] = {0, 0, 0, 0, 0, 0, 0, 0};
        const float* wrow = rp_w + f * 384;
#pragma unroll 4
        for (int k = 0; k < 128; k += 4) {
            float4 wr = *(const float4*)&wrow[128 + k];
            float4 ws = *(const float4*)&wrow[256 + k];
#pragma unroll
            for (int n = 0; n < 8; n++) {
                float4 o = *(const float4*)&Os[n][k];
                r[n] += wr.x * o.x + wr.y * o.y + wr.z * o.z + wr.w * o.w;
                s[n] += ws.x * o.x + ws.y * o.y + ws.z * o.z + ws.w * o.w;
            }
        }
        float bb = rp_b[f];
#pragma unroll
        for (int n = 0; n < 8; n++) {
            g_R[(base + n) * 128 + f] = r[n] + bb;
            g_S[(base + n) * 128 + f] = s[n];
        }
    }
}

// ---------------- fused rel encoder + edge-GEMM (fp16) + edge-apply(step0) ----------------
// 4 bi / block, 512 threads, warp tile 32j x 64f.
__global__ __launch_bounds__(512) void rel_fused_h(const float* __restrict__ rel_attrs,
                                                   const float* __restrict__ re_w0,
                                                   const float* __restrict__ re_b1,
                                                   const float* __restrict__ rp_lnw,
                                                   const float* __restrict__ rp_lnb) {
    extern __shared__ float dsm[];
    float* Ebuf = dsm;
    __half* Hs = (__half*)dsm;                 // 256 x 136 halves
    __half* Wsm = (__half*)(dsm + 32768);      // 128 x 136 halves
    float* Ss = dsm + 32768;                   // 8192 floats (phase 2)
    float* Ps = dsm + 41472;                   // 2048
    float* Us = dsm + 43520;                   // 512
    float* Bss = dsm + 44032;                  // 128
    uint32_t hs_base = (uint32_t)__cvta_generic_to_shared(Hs);
    uint32_t w_base = (uint32_t)__cvta_generic_to_shared(Wsm);

    int bi0 = blockIdx.x * 4;
    int tid = threadIdx.x;
    int b = bi0 >> 6;
    int lane = tid & 31, warp = tid >> 5;
    int jg = warp >> 1;
    int ng = warp & 1;

    Us[tid] = g_u[(bi0 + (tid >> 7)) * 128 + (tid & 127)];
    if (tid < 128) Bss[tid] = re_b1[tid];
    {
        const uint4* src = (const uint4*)g_w1h;
#pragma unroll
        for (int i = 0; i < 4; i++) {
            int idx = i * 512 + tid;
            int row = idx >> 4, part = idx & 15;
            *(uint4*)((char*)Wsm + row * 272 + part * 16) = src[idx];
        }
    }
    __syncthreads();

    // ---- build H[row][k] (fp16) ----
    {
        int bi_l = tid >> 7;
        int j = (tid >> 1) & 63;
        int kh = tid & 1;
        int row = bi_l * 64 + j;
        __half* hrow = Hs + row * 136 + kh * 64;
        float4 rv = *(const float4*)(rel_attrs + ((bi0 + bi_l) * 64 + j) * 4);
        const float* vt = g_vt + b * 8192 + j;
        const float* uu = Us + bi_l * 128;
#pragma unroll
        for (int kk = 0; kk < 64; kk += 8) {
            __half hv[8];
#pragma unroll
            for (int q = 0; q < 8; q++) {
                int k = kh * 64 + kk + q;
                const float* w = re_w0 + k * 20;
                float val = uu[k] + vt[k * 64] + rv.x * w[0] + rv.y * w[1] + rv.z * w[2] + rv.w * w[3];
                hv[q] = __float2half_rn(fmaxf(val, 0.f));
            }
            *(uint4*)(hrow + kk) = *(uint4*)hv;
        }
    }
    __syncthreads();

    int arow = (lane & 7) + ((lane >> 3) & 1) * 8;
    int akoff = (lane >> 4) * 8;
    uint32_t aA0 = hs_base + ((32 * jg + arow) * 136 + akoff) * 2;
    uint32_t aA1 = hs_base + ((32 * jg + 16 + arow) * 136 + akoff) * 2;
    int brow = ((lane >> 4) << 3) + (lane & 7);
    int bkoff = ((lane >> 3) & 1) * 8;
    uint32_t bA[4];
#pragma unroll
    for (int t = 0; t < 4; t++)
        bA[t] = w_base + ((64 * ng + 16 * t + brow) * 136 + bkoff) * 2;

    float d[2][8][4];

    // ================= GEMM1: rel = relu(b1 + H @ W1^T) =================
#pragma unroll
    for (int m = 0; m < 2; m++)
#pragma unroll
        for (int n = 0; n < 8; n++)
#pragma unroll
            for (int q = 0; q < 4; q++) d[m][n][q] = 0.f;
#pragma unroll
    for (int c = 0; c < 8; c++) {
        uint32_t ko = c * 32;
        uint32_t a[2][4];
        LDSM_X4(a[0], aA0 + ko);
        LDSM_X4(a[1], aA1 + ko);
#pragma unroll
        for (int t = 0; t < 4; t++) {
            uint32_t bb[4];
            LDSM_X4(bb, bA[t] + ko);
            MMA_F16(d[0][2 * t], a[0], bb[0], bb[1]);
            MMA_F16(d[1][2 * t], a[1], bb[0], bb[1]);
            MMA_F16(d[0][2 * t + 1], a[0], bb[2], bb[3]);
            MMA_F16(d[1][2 * t + 1], a[1], bb[2], bb[3]);
        }
    }
    __syncthreads();

    // epilogue 1: bias + relu -> fp16 rel back into Hs; reload Wr into Wsm
#pragma unroll
    for (int m = 0; m < 2; m++) {
        int r0 = 32 * jg + 16 * m + (lane >> 2);
#pragma unroll
        for (int n = 0; n < 8; n++) {
            int f0 = 64 * ng + 8 * n + 2 * (lane & 3);
            float bb0 = Bss[f0], bb1 = Bss[f0 + 1];
            __half2 v01 = __floats2half2_rn(fmaxf(d[m][n][0] + bb0, 0.f),
                                            fmaxf(d[m][n][1] + bb1, 0.f));
            __half2 v23 = __floats2half2_rn(fmaxf(d[m][n][2] + bb0, 0.f),
                                            fmaxf(d[m][n][3] + bb1, 0.f));
            *(__half2*)(Hs + r0 * 136 + f0) = v01;
            *(__half2*)(Hs + (r0 + 8) * 136 + f0) = v23;
        }
    }
    {
        const uint4* src = (const uint4*)g_wrh;
#pragma unroll
        for (int i = 0; i < 4; i++) {
            int idx = i * 512 + tid;
            int row = idx >> 4, part = idx & 15;
            *(uint4*)((char*)Wsm + row * 272 + part * 16) = src[idx];
        }
    }
    __syncthreads();

    // ================= GEMM2: E = rel @ Wr^T =================
#pragma unroll
    for (int m = 0; m < 2; m++)
#pragma unroll
        for (int n = 0; n < 8; n++)
#pragma unroll
            for (int q = 0; q < 4; q++) d[m][n][q] = 0.f;
#pragma unroll
    for (int c = 0; c < 8; c++) {
        uint32_t ko = c * 32;
        uint32_t a[2][4];
        LDSM_X4(a[0], aA0 + ko);
        LDSM_X4(a[1], aA1 + ko);
#pragma unroll
        for (int t = 0; t < 4; t++) {
            uint32_t bb[4];
            LDSM_X4(bb, bA[t] + ko);
            MMA_F16(d[0][2 * t], a[0], bb[0], bb[1]);
            MMA_F16(d[1][2 * t], a[1], bb[0], bb[1]);
            MMA_F16(d[0][2 * t + 1], a[0], bb[2], bb[3]);
            MMA_F16(d[1][2 * t + 1], a[1], bb[2], bb[3]);
        }
    }
    __syncthreads();

    // epilogue 2: E -> g_Eh (fp16) and Ebuf (fp32 smem)
    __half* Ep = g_Eh + (long)bi0 * 8192;
#pragma unroll
    for (int m = 0; m < 2; m++) {
        int r0 = 32 * jg + 16 * m + (lane >> 2);
#pragma unroll
        for (int n = 0; n < 8; n++) {
            int f0 = 64 * ng + 8 * n + 2 * (lane & 3);
            *(__half2*)&Ep[r0 * 128 + f0] = __floats2half2_rn(d[m][n][0], d[m][n][1]);
            *(__half2*)&Ep[(r0 + 8) * 128 + f0] = __floats2half2_rn(d[m][n][2], d[m][n][3]);
            *(float2*)&Ebuf[r0 * 128 + f0] = make_float2(d[m][n][0], d[m][n][1]);
            *(float2*)&Ebuf[(r0 + 8) * 128 + f0] = make_float2(d[m][n][2], d[m][n][3]);
        }
    }
#pragma unroll
    for (int i = 0; i < 4; i++) {
        int idx4 = (i * 512 + tid) * 4;
        *(float4*)&Ss[idx4] = *(const float4*)&g_S[b * 8192 + idx4];
    }
    Us[tid] = g_R[bi0 * 128 + tid];
    __syncthreads();

    // ---- fused edge-apply step 0 ----
    {
        int bi_l = warp >> 2;
        float4 rv = *(const float4*)&Us[bi_l * 128 + lane * 4];
        float4 lw = *(const float4*)&rp_lnw[lane * 4];
        float4 lb = *(const float4*)&rp_lnb[lane * 4];
        float ag0 = 0.f, ag1 = 0.f, ag2 = 0.f, ag3 = 0.f;
#pragma unroll 4
        for (int rr = 0; rr < 16; rr++) {
            int r = warp * 16 + rr;
            int j = r & 63;
            float4 e = *(const float4*)&Ebuf[r * 128 + lane * 4];
            float4 sv = *(const float4*)&Ss[j * 128 + lane * 4];
            float4 y = make_float4(e.x + rv.x + sv.x, e.y + rv.y + sv.y,
                                   e.z + rv.z + sv.z, e.w + rv.w + sv.w);
            float s = y.x + y.y + y.z + y.w;
            float ss = y.x * y.x + y.y * y.y + y.z * y.z + y.w * y.w;
#pragma unroll
            for (int off = 16; off; off >>= 1) {
                s += __shfl_xor_sync(0xffffffffu, s, off);
                ss += __shfl_xor_sync(0xffffffffu, ss, off);
            }
            float mu = s * 0.0078125f;
            float var = ss * 0.0078125f - mu * mu;
            float rstd = rsqrtf(var + 1e-5f);
            ag0 += fmaxf((y.x - mu) * rstd * lw.x + lb.x, 0.f);
            ag1 += fmaxf((y.y - mu) * rstd * lw.y + lb.y, 0.f);
            ag2 += fmaxf((y.z - mu) * rstd * lw.z + lb.z, 0.f);
            ag3 += fmaxf((y.w - mu) * rstd * lw.w + lb.w, 0.f);
        }
        *(float4*)&Ps[warp * 128 + lane * 4] = make_float4(ag0, ag1, ag2, ag3);
    }
    __syncthreads();
    {
        int bi_l = tid >> 7, f = tid & 127;
        g_agg[(bi0 + bi_l) * 128 + f] =
            Ps[(4 * bi_l) * 128 + f] + Ps[(4 * bi_l + 1) * 128 + f] +
            Ps[(4 * bi_l + 2) * 128 + f] + Ps[(4 * bi_l + 3) * 128 + f];
    }
}

// ---------------- edge apply (step 1): fp16 E ----------------
__global__ __launch_bounds__(128) void edge_apply_kernel(const float* __restrict__ rp_lnw,
                                                         const float* __restrict__ rp_lnb) {
    __shared__ float Rs[128];
    __shared__ float Ps[512];
    int bi = blockIdx.x;
    int tid = threadIdx.x;
    int b = bi >> 6;
    int warp = tid >> 5, lane = tid & 31;
    Rs[tid] = g_R[bi * 128 + tid];
    __syncthreads();
    float4 rv = *(const float4*)&Rs[lane * 4];
    float4 lw = *(const float4*)&rp_lnw[lane * 4];
    float4 lb = *(const float4*)&rp_lnb[lane * 4];
    const __half* Ep = g_Eh + (long)bi * 8192;
    float ag0 = 0.f, ag1 = 0.f, ag2 = 0.f, ag3 = 0.f;
#pragma unroll 4
    for (int r = 0; r < 16; r++) {
        int j = warp * 16 + r;
        __half2 e01h = *(const __half2*)&Ep[j * 128 + lane * 4];
        __half2 e23h = *(const __half2*)&Ep[j * 128 + lane * 4 + 2];
        float2 e01 = __half22float2(e01h);
        float2 e23 = __half22float2(e23h);
        float4 sv = *(const float4*)&g_S[(b * 64 + j) * 128 + lane * 4];
        float4 y = make_float4(e01.x + rv.x + sv.x, e01.y + rv.y + sv.y,
                               e23.x + rv.z + sv.z, e23.y + rv.w + sv.w);
        float s = y.x + y.y + y.z + y.w;
        float ss = y.x * y.x + y.y * y.y + y.z * y.z + y.w * y.w;
#pragma unroll
        for (int off = 16; off; off >>= 1) {
            s += __shfl_xor_sync(0xffffffffu, s, off);
            ss += __shfl_xor_sync(0xffffffffu, ss, off);
        }
        float mu = s * 0.0078125f;
        float var = ss * 0.0078125f - mu * mu;
        float rstd = rsqrtf(var + 1e-5f);
        ag0 += fmaxf((y.x - mu) * rstd * lw.x + lb.x, 0.f);
        ag1 += fmaxf((y.y - mu) * rstd * lw.y + lb.y, 0.f);
        ag2 += fmaxf((y.z - mu) * rstd * lw.z + lb.z, 0.f);
        ag3 += fmaxf((y.w - mu) * rstd * lw.w + lb.w, 0.f);
    }
    *(float4*)&Ps[warp * 128 + lane * 4] = make_float4(ag0, ag1, ag2, ag3);
    __syncthreads();
    g_agg[bi * 128 + tid] = Ps[tid] + Ps[128 + tid] + Ps[256 + tid] + Ps[384 + tid];
}

// ---------------- fused object update (+rs or +predict): 8 nodes/block, 512 thr, grid 256 ----------------
__global__ __launch_bounds__(512) void obj_update_f(const float* __restrict__ pp_w,
                                                    const float* __restrict__ pp_b,
                                                    const float* __restrict__ pp_lnw,
                                                    const float* __restrict__ pp_lnb,
                                                    const float* __restrict__ rp_w,
                                                    const float* __restrict__ rp_b,
                                                    const float* __restrict__ pr_w0,
                                                    const float* __restrict__ pr_b0,
                                                    const float* __restrict__ pr_w1,
                                                    const float* __restrict__ pr_b1,
                                                    float* __restrict__ out,
                                                    int mode) {  // 0: +rs, 1: +predict
    extern __shared__ float sm[];
    float* Xs   = sm;            // [8][256]  = 2048
    float* part = sm + 2048;     // 4096
    float* Cs   = sm + 6144;     // [8][128]  = 1024
    float* Os2  = sm + 7168;     // [8][128]  = 1024
    float* Hs2  = sm + 8192;     // [8][128]  = 1024
    int base = blockIdx.x * 8;
    int tid = threadIdx.x;
    int warp = tid >> 5, lane = tid & 31;

#pragma unroll
    for (int i = 0; i < 4; i++) {
        int idx = i * 512 + tid;
        int n = idx >> 8, c = idx & 255;
        Xs[idx] = (c < 128) ? g_obj[(base + n) * 128 + c]
                            : g_agg[(base + n) * 128 + (c - 128)];
    }
    __syncthreads();

    // ---- phase 1: pp GEMV, 4-way k-split ----
    {
        int f = tid & 127, q = tid >> 7;
        float acc[8] = {0, 0, 0, 0, 0, 0, 0, 0};
        const float* wrow = pp_w + f * 256 + q * 64;
        const float* xb = Xs + q * 64;
#pragma unroll 4
        for (int k = 0; k < 64; k += 4) {
            float4 w = *(const float4*)&wrow[k];
#pragma unroll
            for (int n = 0; n < 8; n++) {
                float4 x = *(const float4*)&xb[n * 256 + k];
                acc[n] += w.x * x.x + w.y * x.y + w.z * x.z + w.w * x.w;
            }
        }
#pragma unroll
        for (int n = 0; n < 8; n++) part[q * 1024 + n * 128 + f] = acc[n];
    }
    __syncthreads();
#pragma unroll
    for (int i = 0; i < 2; i++) {
        int idx = i * 512 + tid;   // 1024 outputs: n = idx>>7, f = idx&127
        float v = part[idx] + part[1024 + idx] + part[2048 + idx] + part[3072 + idx];
        Cs[idx] = v + pp_b[idx & 127];
    }
    __syncthreads();

    // ---- phase 2: LN, one warp per node (warps 0-7) ----
    if (warp < 8) {
        float4 lw = *(const float4*)&pp_lnw[lane * 4];
        float4 lb = *(const float4*)&pp_lnb[lane * 4];
        int n = warp;
        float4 y = *(const float4*)&Cs[n * 128 + lane * 4];
        float s = y.x + y.y + y.z + y.w;
        float ss = y.x * y.x + y.y * y.y + y.z * y.z + y.w * y.w;
#pragma unroll
        for (int off = 16; off; off >>= 1) {
            s += __shfl_xor_sync(0xffffffffu, s, off);
            ss += __shfl_xor_sync(0xffffffffu, ss, off);
        }
        float mu = s * 0.0078125f;
        float var = ss * 0.0078125f - mu * mu;
        float rstd = rsqrtf(var + 1e-5f);
        float4 o = make_float4(fmaxf((y.x - mu) * rstd * lw.x + lb.x, 0.f),
                               fmaxf((y.y - mu) * rstd * lw.y + lb.y, 0.f),
                               fmaxf((y.z - mu) * rstd * lw.z + lb.z, 0.f),
                               fmaxf((y.w - mu) * rstd * lw.w + lb.w, 0.f));
        *(float4*)&Os2[n * 128 + lane * 4] = o;
        if (mode == 0) *(float4*)&g_obj[(base + n) * 128 + lane * 4] = o;
    }
    __syncthreads();

    if (mode == 0) {
        // ---- rs: 256 outputs/node (R|S), 2-way k-split ----
        int fo = tid & 255, q = tid >> 8;
        float acc[8] = {0, 0, 0, 0, 0, 0, 0, 0};
        const float* wrow = (fo < 128) ? (rp_w + fo * 384 + 128 + q * 64)
                                       : (rp_w + (fo - 128) * 384 + 256 + q * 64);
        const float* ob = Os2 + q * 64;
#pragma unroll 4
        for (int k = 0; k < 64; k += 4) {
            float4 w = *(const float4*)&wrow[k];
#pragma unroll
            for (int n = 0; n < 8; n++) {
                float4 x = *(const float4*)&ob[n * 128 + k];
                acc[n] += w.x * x.x + w.y * x.y + w.z * x.z + w.w * x.w;
            }
        }
#pragma unroll
        for (int n = 0; n < 8; n++) part[q * 2048 + n * 256 + fo] = acc[n];
        __syncthreads();
#pragma unroll
        for (int i = 0; i < 4; i++) {
            int idx = i * 512 + tid;  // 2048 outputs: n = idx>>8, fo = idx&255
            float v = part[idx] + part[2048 + idx];
            int n = idx >> 8, fo2 = idx & 255;
            if (fo2 < 128) g_R[(base + n) * 128 + fo2] = v + rp_b[fo2];
            else g_S[(base + n) * 128 + fo2 - 128] = v;
        }
    } else {
        // ---- predict layer1: 4-way k-split ----
        {
            int f = tid & 127, q = tid >> 7;
            float acc[8] = {0, 0, 0, 0, 0, 0, 0, 0};
            const float* wrow = pr_w0 + f * 128 + q * 32;
            const float* ob = Os2 + q * 32;
#pragma unroll 4
            for (int k = 0; k < 32; k += 4) {
                float4 w = *(const float4*)&wrow[k];
#pragma unroll
                for (int n = 0; n < 8; n++) {
                    float4 x = *(const float4*)&ob[n * 128 + k];
                    acc[n] += w.x * x.x + w.y * x.y + w.z * x.z + w.w * x.w;
                }
            }
#pragma unroll
            for (int n = 0; n < 8; n++) part[q * 1024 + n * 128 + f] = acc[n];
        }
        __syncthreads();
#pragma unroll
        for (int i = 0; i < 2; i++) {
            int idx = i * 512 + tid;
            float v = part[idx] + part[1024 + idx] + part[2048 + idx] + part[3072 + idx];
            Hs2[idx] = fmaxf(v + pr_b0[idx & 127], 0.f);
        }
        __syncthreads();
        // ---- predict layer2: 256 outputs, threads 0-255 ----
        if (tid < 256) {
            int n = tid >> 5, op = tid & 31;
            float a0 = 0.f;
            const float* wp = pr_w1 + op * 128;
#pragma unroll 4
            for (int k = 0; k < 128; k += 4) {
                float4 x = *(const float4*)&Hs2[n * 128 + k];
                float4 w = *(const float4*)&wp[k];
                a0 += w.x * x.x + w.y * x.y + w.z * x.z + w.w * x.w;
            }
            out[(base + n) * 32 + op] = tanhf(a0 + pr_b1[op]);
        }
    }
}

// ---------------- launch ----------------
extern "C" void kernel_launch(void* const* d_in, const int* in_sizes, int n_in,
                              void* d_out, int out_size) {
    const float* attrs     = (const float*)d_in[0];
    const float* states    = (const float*)d_in[1];
    const float* rel_attrs = (const float*)d_in[3];
    const float* oe_w0 = (const float*)d_in[4];
    const float* oe_b0 = (const float*)d_in[5];
    const float* oe_w1 = (const float*)d_in[6];
    const float* oe_b1 = (const float*)d_in[7];
    const float* re_w0 = (const float*)d_in[8];
    const float* re_b0 = (const float*)d_in[9];
    const float* re_w1 = (const float*)d_in[10];
    const float* re_b1 = (const float*)d_in[11];
    const float* rp_w  = (const float*)d_in[12];
    const float* rp_b  = (const float*)d_in[13];
    const float* rp_lnw = (const float*)d_in[14];
    const float* rp_lnb = (const float*)d_in[15];
    const float* pp_w  = (const float*)d_in[16];
    const float* pp_b  = (const float*)d_in[17];
    const float* pp_lnw = (const float*)d_in[18];
    const float* pp_lnb = (const float*)d_in[19];
    const float* pr_w0 = (const float*)d_in[20];
    const float* pr_b0 = (const float*)d_in[21];
    const float* pr_w1 = (const float*)d_in[22];
    const float* pr_b1 = (const float*)d_in[23];
    float* out = (float*)d_out;

    const int dsm_bytes = 44160 * 4;   // ~172.5 KB
    const int ou_bytes  = 9216 * 4;    // 36 KB
    cudaFuncSetAttribute(rel_fused_h, cudaFuncAttributeMaxDynamicSharedMemorySize, dsm_bytes);
    cudaFuncSetAttribute(obj_update_f, cudaFuncAttributeMaxDynamicSharedMemorySize, ou_bytes);

    encode_all<<<256, 128>>>(attrs, states, re_w0, re_b0, oe_w0, oe_b0, oe_w1, oe_b1,
                             re_w1, rp_w, rp_b);
    rel_fused_h<<<512, 512, dsm_bytes>>>(rel_attrs, re_w0, re_b1, rp_lnw, rp_lnb);
    obj_update_f<<<256, 512, ou_bytes>>>(pp_w, pp_b, pp_lnw, pp_lnb, rp_w, rp_b,
                                         pr_w0, pr_b0, pr_w1, pr_b1, out, 0);
    edge_apply_kernel<<<NNODES, 128>>>(rp_lnw, rp_lnb);
    obj_update_f<<<256, 512, ou_bytes>>>(pp_w, pp_b, pp_lnw, pp_lnb, rp_w, rp_b,
                                         pr_w0, pr_b0, pr_w1, pr_b1, out, 1);
}

// round 16
// speedup vs baseline: 1.0843x; 1.0843x over previous
#include <cuda_runtime.h>
#include <cuda_fp16.h>
#include <stdint.h>
#include <math.h>

// B=32, N=64, ATTR=4, STATE=8, REL=4, GDIM=32, NF=128, pstep=2
#define NNODES 2048

// ---------------- scratch (static device memory) ----------------
__device__ __half g_Eh[2048 * 64 * 128];   // E, [bi][j][f] fp16 (32 MB)
__device__ float g_obj[2048 * 128];
__device__ float g_u[2048 * 128];
__device__ float g_vt[32 * 128 * 64];      // [b][k][n]
__device__ float g_R[2048 * 128];
__device__ float g_S[2048 * 128];
__device__ float g_agg[2048 * 128];
__device__ __half g_w1h[128 * 128];        // re_w1 [f][k] fp16
__device__ __half g_wrh[128 * 128];        // rp_w rel-block [f][k] fp16

#define LDSM_X4(r, addr)                                                      \
    asm volatile("ldmatrix.sync.aligned.m8n8.x4.shared.b16 {%0,%1,%2,%3}, [%4];" \
                 : "=r"((r)[0]), "=r"((r)[1]), "=r"((r)[2]), "=r"((r)[3])     \
                 : "r"(addr))

#define MMA_F16(d, a, b0v, b1v)                                               \
    asm volatile(                                                             \
        "mma.sync.aligned.m16n8k16.row.col.f32.f16.f16.f32 "                  \
        "{%0,%1,%2,%3}, {%4,%5,%6,%7}, {%8,%9}, {%0,%1,%2,%3};"               \
        : "+f"((d)[0]), "+f"((d)[1]), "+f"((d)[2]), "+f"((d)[3])              \
        : "r"((a)[0]), "r"((a)[1]), "r"((a)[2]), "r"((a)[3]),                 \
          "r"(b0v), "r"(b1v))

// ---------------- fused prep + node_pre + obj_encode + rs(step0): 8 nodes/block ----------------
__global__ __launch_bounds__(128) void encode_all(const float* __restrict__ attrs,
                                                  const float* __restrict__ states,
                                                  const float* __restrict__ re_w0,
                                                  const float* __restrict__ re_b0,
                                                  const float* __restrict__ oe_w0,
                                                  const float* __restrict__ oe_b0,
                                                  const float* __restrict__ oe_w1,
                                                  const float* __restrict__ oe_b1,
                                                  const float* __restrict__ re_w1,
                                                  const float* __restrict__ rp_w,
                                                  const float* __restrict__ rp_b) {
    {
        int gidx = blockIdx.x * 128 + threadIdx.x;
        if (gidx < 16384) {
            g_w1h[gidx] = __float2half_rn(re_w1[gidx]);
        } else {
            int i = gidx - 16384;
            int f = i >> 7, k = i & 127;
            g_wrh[i] = __float2half_rn(rp_w[f * 384 + k]);
        }
    }
    __shared__ float sa[8][4];
    __shared__ float ssm[8][8];
    __shared__ float Hs1[8][128];
    __shared__ float Os[8][128];
    int base = blockIdx.x * 8;
    int f = threadIdx.x;
    if (f < 32) {
        int n = f >> 2, c = f & 3;
        sa[n][c] = attrs[(base + n) * 4 + c];
    } else if (f < 96) {
        int q = f - 32;
        int n = q >> 3, c = q & 7;
        ssm[n][c] = states[(base + n) * 8 + c];
    }
    __syncthreads();
    {
        const float* w = re_w0 + f * 20;
        float ws[8], wr4[4], ws4[4];
#pragma unroll
        for (int c = 0; c < 8; c++) ws[c] = w[4 + c];
#pragma unroll
        for (int c = 0; c < 4; c++) { wr4[c] = w[12 + c]; ws4[c] = w[16 + c]; }
        float b0 = re_b0[f];
        int b = base >> 6;
#pragma unroll
        for (int n = 0; n < 8; n++) {
            float u = b0, v = 0.f;
#pragma unroll
            for (int c = 0; c < 8; c++) {
                u += ws[c] * ssm[n][c];
                v -= ws[c] * ssm[n][c];
            }
#pragma unroll
            for (int c = 0; c < 4; c++) {
                u += wr4[c] * sa[n][c];
                v += ws4[c] * sa[n][c];
            }
            int node = base + n;
            g_u[node * 128 + f] = u;
            g_vt[(b * 128 + f) * 64 + (node & 63)] = v;
        }
    }
    {
        float w0r[12];
#pragma unroll
        for (int c = 0; c < 12; c++) w0r[c] = oe_w0[f * 12 + c];
        float b0 = oe_b0[f];
#pragma unroll
        for (int n = 0; n < 8; n++) {
            float h = b0;
#pragma unroll
            for (int c = 0; c < 4; c++) h += w0r[c] * sa[n][c];
#pragma unroll
            for (int c = 0; c < 8; c++) h += w0r[4 + c] * ssm[n][c];
            Hs1[n][f] = fmaxf(h, 0.f);
        }
    }
    __syncthreads();
    {
        float acc[8] = {0, 0, 0, 0, 0, 0, 0, 0};
#pragma unroll 4
        for (int k = 0; k < 128; k += 4) {
            float4 w = *(const float4*)&oe_w1[f * 128 + k];
#pragma unroll
            for (int n = 0; n < 8; n++) {
                float4 x = *(const float4*)&Hs1[n][k];
                acc[n] += w.x * x.x + w.y * x.y + w.z * x.z + w.w * x.w;
            }
        }
        float b1 = oe_b1[f];
#pragma unroll
        for (int n = 0; n < 8; n++) {
            float o = fmaxf(acc[n] + b1, 0.f);
            Os[n][f] = o;
            g_obj[(base + n) * 128 + f] = o;
        }
    }
    __syncthreads();
    {
        float r[8] = {0, 0, 0, 0, 0, 0, 0, 0};
        float s[8] = {0, 0, 0, 0, 0, 0, 0, 0};
        const float* wrow = rp_w + f * 384;
#pragma unroll 4
        for (int k = 0; k < 128; k += 4) {
            float4 wr = *(const float4*)&wrow[128 + k];
            float4 ws = *(const float4*)&wrow[256 + k];
#pragma unroll
            for (int n = 0; n < 8; n++) {
                float4 o = *(const float4*)&Os[n][k];
                r[n] += wr.x * o.x + wr.y * o.y + wr.z * o.z + wr.w * o.w;
                s[n] += ws.x * o.x + ws.y * o.y + ws.z * o.z + ws.w * o.w;
            }
        }
        float bb = rp_b[f];
#pragma unroll
        for (int n = 0; n < 8; n++) {
            g_R[(base + n) * 128 + f] = r[n] + bb;
            g_S[(base + n) * 128 + f] = s[n];
        }
    }
}

// ---------------- fused rel encoder + edge-GEMM (fp16) + edge-apply(step0) ----------------
__global__ __launch_bounds__(512) void rel_fused_h(const float* __restrict__ rel_attrs,
                                                   const float* __restrict__ re_w0,
                                                   const float* __restrict__ re_b1,
                                                   const float* __restrict__ rp_lnw,
                                                   const float* __restrict__ rp_lnb) {
    extern __shared__ float dsm[];
    float* Ebuf = dsm;
    __half* Hs = (__half*)dsm;                 // 256 x 136 halves
    __half* Wsm = (__half*)(dsm + 32768);      // 128 x 136 halves
    float* Ss = dsm + 32768;                   // 8192 floats (phase 2)
    float* Ps = dsm + 41472;                   // 2048
    float* Us = dsm + 43520;                   // 512
    float* Bss = dsm + 44032;                  // 128
    uint32_t hs_base = (uint32_t)__cvta_generic_to_shared(Hs);
    uint32_t w_base = (uint32_t)__cvta_generic_to_shared(Wsm);

    int bi0 = blockIdx.x * 4;
    int tid = threadIdx.x;
    int b = bi0 >> 6;
    int lane = tid & 31, warp = tid >> 5;
    int jg = warp >> 1;
    int ng = warp & 1;

    Us[tid] = g_u[(bi0 + (tid >> 7)) * 128 + (tid & 127)];
    if (tid < 128) Bss[tid] = re_b1[tid];
    {
        const uint4* src = (const uint4*)g_w1h;
#pragma unroll
        for (int i = 0; i < 4; i++) {
            int idx = i * 512 + tid;
            int row = idx >> 4, part = idx & 15;
            *(uint4*)((char*)Wsm + row * 272 + part * 16) = src[idx];
        }
    }
    __syncthreads();

    // ---- build H[row][k] (fp16) ----
    {
        int bi_l = tid >> 7;
        int j = (tid >> 1) & 63;
        int kh = tid & 1;
        int row = bi_l * 64 + j;
        __half* hrow = Hs + row * 136 + kh * 64;
        float4 rv = *(const float4*)(rel_attrs + ((bi0 + bi_l) * 64 + j) * 4);
        const float* vt = g_vt + b * 8192 + j;
        const float* uu = Us + bi_l * 128;
#pragma unroll
        for (int kk = 0; kk < 64; kk += 8) {
            __half hv[8];
#pragma unroll
            for (int q = 0; q < 8; q++) {
                int k = kh * 64 + kk + q;
                const float* w = re_w0 + k * 20;
                float val = uu[k] + vt[k * 64] + rv.x * w[0] + rv.y * w[1] + rv.z * w[2] + rv.w * w[3];
                hv[q] = __float2half_rn(fmaxf(val, 0.f));
            }
            *(uint4*)(hrow + kk) = *(uint4*)hv;
        }
    }
    __syncthreads();

    int arow = (lane & 7) + ((lane >> 3) & 1) * 8;
    int akoff = (lane >> 4) * 8;
    uint32_t aA0 = hs_base + ((32 * jg + arow) * 136 + akoff) * 2;
    uint32_t aA1 = hs_base + ((32 * jg + 16 + arow) * 136 + akoff) * 2;
    int brow = ((lane >> 4) << 3) + (lane & 7);
    int bkoff = ((lane >> 3) & 1) * 8;
    uint32_t bA[4];
#pragma unroll
    for (int t = 0; t < 4; t++)
        bA[t] = w_base + ((64 * ng + 16 * t + brow) * 136 + bkoff) * 2;

    float d[2][8][4];

    // ================= GEMM1: rel = relu(b1 + H @ W1^T) =================
#pragma unroll
    for (int m = 0; m < 2; m++)
#pragma unroll
        for (int n = 0; n < 8; n++)
#pragma unroll
            for (int q = 0; q < 4; q++) d[m][n][q] = 0.f;
#pragma unroll
    for (int c = 0; c < 8; c++) {
        uint32_t ko = c * 32;
        uint32_t a[2][4];
        LDSM_X4(a[0], aA0 + ko);
        LDSM_X4(a[1], aA1 + ko);
#pragma unroll
        for (int t = 0; t < 4; t++) {
            uint32_t bb[4];
            LDSM_X4(bb, bA[t] + ko);
            MMA_F16(d[0][2 * t], a[0], bb[0], bb[1]);
            MMA_F16(d[1][2 * t], a[1], bb[0], bb[1]);
            MMA_F16(d[0][2 * t + 1], a[0], bb[2], bb[3]);
            MMA_F16(d[1][2 * t + 1], a[1], bb[2], bb[3]);
        }
    }
    __syncthreads();

    // epilogue 1: bias + relu -> fp16 rel back into Hs; reload Wr into Wsm
#pragma unroll
    for (int m = 0; m < 2; m++) {
        int r0 = 32 * jg + 16 * m + (lane >> 2);
#pragma unroll
        for (int n = 0; n < 8; n++) {
            int f0 = 64 * ng + 8 * n + 2 * (lane & 3);
            float bb0 = Bss[f0], bb1 = Bss[f0 + 1];
            __half2 v01 = __floats2half2_rn(fmaxf(d[m][n][0] + bb0, 0.f),
                                            fmaxf(d[m][n][1] + bb1, 0.f));
            __half2 v23 = __floats2half2_rn(fmaxf(d[m][n][2] + bb0, 0.f),
                                            fmaxf(d[m][n][3] + bb1, 0.f));
            *(__half2*)(Hs + r0 * 136 + f0) = v01;
            *(__half2*)(Hs + (r0 + 8) * 136 + f0) = v23;
        }
    }
    {
        const uint4* src = (const uint4*)g_wrh;
#pragma unroll
        for (int i = 0; i < 4; i++) {
            int idx = i * 512 + tid;
            int row = idx >> 4, part = idx & 15;
            *(uint4*)((char*)Wsm + row * 272 + part * 16) = src[idx];
        }
    }
    __syncthreads();

    // ================= GEMM2: E = rel @ Wr^T =================
#pragma unroll
    for (int m = 0; m < 2; m++)
#pragma unroll
        for (int n = 0; n < 8; n++)
#pragma unroll
            for (int q = 0; q < 4; q++) d[m][n][q] = 0.f;
#pragma unroll
    for (int c = 0; c < 8; c++) {
        uint32_t ko = c * 32;
        uint32_t a[2][4];
        LDSM_X4(a[0], aA0 + ko);
        LDSM_X4(a[1], aA1 + ko);
#pragma unroll
        for (int t = 0; t < 4; t++) {
            uint32_t bb[4];
            LDSM_X4(bb, bA[t] + ko);
            MMA_F16(d[0][2 * t], a[0], bb[0], bb[1]);
            MMA_F16(d[1][2 * t], a[1], bb[0], bb[1]);
            MMA_F16(d[0][2 * t + 1], a[0], bb[2], bb[3]);
            MMA_F16(d[1][2 * t + 1], a[1], bb[2], bb[3]);
        }
    }
    __syncthreads();

    // epilogue 2: E -> g_Eh (fp16) and Ebuf (fp32 smem)
    __half* Ep = g_Eh + (long)bi0 * 8192;
#pragma unroll
    for (int m = 0; m < 2; m++) {
        int r0 = 32 * jg + 16 * m + (lane >> 2);
#pragma unroll
        for (int n = 0; n < 8; n++) {
            int f0 = 64 * ng + 8 * n + 2 * (lane & 3);
            *(__half2*)&Ep[r0 * 128 + f0] = __floats2half2_rn(d[m][n][0], d[m][n][1]);
            *(__half2*)&Ep[(r0 + 8) * 128 + f0] = __floats2half2_rn(d[m][n][2], d[m][n][3]);
            *(float2*)&Ebuf[r0 * 128 + f0] = make_float2(d[m][n][0], d[m][n][1]);
            *(float2*)&Ebuf[(r0 + 8) * 128 + f0] = make_float2(d[m][n][2], d[m][n][3]);
        }
    }
#pragma unroll
    for (int i = 0; i < 4; i++) {
        int idx4 = (i * 512 + tid) * 4;
        *(float4*)&Ss[idx4] = *(const float4*)&g_S[b * 8192 + idx4];
    }
    Us[tid] = g_R[bi0 * 128 + tid];
    __syncthreads();

    // ---- fused edge-apply step 0 ----
    {
        int bi_l = warp >> 2;
        float4 rv = *(const float4*)&Us[bi_l * 128 + lane * 4];
        float4 lw = *(const float4*)&rp_lnw[lane * 4];
        float4 lb = *(const float4*)&rp_lnb[lane * 4];
        float ag0 = 0.f, ag1 = 0.f, ag2 = 0.f, ag3 = 0.f;
#pragma unroll 4
        for (int rr = 0; rr < 16; rr++) {
            int r = warp * 16 + rr;
            int j = r & 63;
            float4 e = *(const float4*)&Ebuf[r * 128 + lane * 4];
            float4 sv = *(const float4*)&Ss[j * 128 + lane * 4];
            float4 y = make_float4(e.x + rv.x + sv.x, e.y + rv.y + sv.y,
                                   e.z + rv.z + sv.z, e.w + rv.w + sv.w);
            float s = y.x + y.y + y.z + y.w;
            float ss = y.x * y.x + y.y * y.y + y.z * y.z + y.w * y.w;
#pragma unroll
            for (int off = 16; off; off >>= 1) {
                s += __shfl_xor_sync(0xffffffffu, s, off);
                ss += __shfl_xor_sync(0xffffffffu, ss, off);
            }
            float mu = s * 0.0078125f;
            float var = ss * 0.0078125f - mu * mu;
            float rstd = rsqrtf(var + 1e-5f);
            ag0 += fmaxf((y.x - mu) * rstd * lw.x + lb.x, 0.f);
            ag1 += fmaxf((y.y - mu) * rstd * lw.y + lb.y, 0.f);
            ag2 += fmaxf((y.z - mu) * rstd * lw.z + lb.z, 0.f);
            ag3 += fmaxf((y.w - mu) * rstd * lw.w + lb.w, 0.f);
        }
        *(float4*)&Ps[warp * 128 + lane * 4] = make_float4(ag0, ag1, ag2, ag3);
    }
    __syncthreads();
    {
        int bi_l = tid >> 7, f = tid & 127;
        g_agg[(bi0 + bi_l) * 128 + f] =
            Ps[(4 * bi_l) * 128 + f] + Ps[(4 * bi_l + 1) * 128 + f] +
            Ps[(4 * bi_l + 2) * 128 + f] + Ps[(4 * bi_l + 3) * 128 + f];
    }
}

// ---------------- edge apply (step 1): 4 bi/block, S staged in smem, fp16 E ----------------
__global__ __launch_bounds__(512) void edge_apply_v2(const float* __restrict__ rp_lnw,
                                                     const float* __restrict__ rp_lnb) {
    __shared__ float Ss[8192];
    __shared__ float Ps[2048];
    __shared__ float Rs[512];
    int bi0 = blockIdx.x * 4;
    int tid = threadIdx.x;
    int b = bi0 >> 6;
    int lane = tid & 31, warp = tid >> 5;
#pragma unroll
    for (int i = 0; i < 4; i++) {
        int idx4 = (i * 512 + tid) * 4;
        *(float4*)&Ss[idx4] = *(const float4*)&g_S[b * 8192 + idx4];
    }
    Rs[tid] = g_R[bi0 * 128 + tid];
    __syncthreads();
    {
        int bi_l = warp >> 2;
        float4 rv = *(const float4*)&Rs[bi_l * 128 + lane * 4];
        float4 lw = *(const float4*)&rp_lnw[lane * 4];
        float4 lb = *(const float4*)&rp_lnb[lane * 4];
        const __half* Ep = g_Eh + (long)(bi0 + bi_l) * 8192;
        float ag0 = 0.f, ag1 = 0.f, ag2 = 0.f, ag3 = 0.f;
#pragma unroll 4
        for (int rr = 0; rr < 16; rr++) {
            int j = (warp & 3) * 16 + rr;
            __half2 e01h = *(const __half2*)&Ep[j * 128 + lane * 4];
            __half2 e23h = *(const __half2*)&Ep[j * 128 + lane * 4 + 2];
            float2 e01 = __half22float2(e01h);
            float2 e23 = __half22float2(e23h);
            float4 sv = *(const float4*)&Ss[j * 128 + lane * 4];
            float4 y = make_float4(e01.x + rv.x + sv.x, e01.y + rv.y + sv.y,
                                   e23.x + rv.z + sv.z, e23.y + rv.w + sv.w);
            float s = y.x + y.y + y.z + y.w;
            float ss = y.x * y.x + y.y * y.y + y.z * y.z + y.w * y.w;
#pragma unroll
            for (int off = 16; off; off >>= 1) {
                s += __shfl_xor_sync(0xffffffffu, s, off);
                ss += __shfl_xor_sync(0xffffffffu, ss, off);
            }
            float mu = s * 0.0078125f;
            float var = ss * 0.0078125f - mu * mu;
            float rstd = rsqrtf(var + 1e-5f);
            ag0 += fmaxf((y.x - mu) * rstd * lw.x + lb.x, 0.f);
            ag1 += fmaxf((y.y - mu) * rstd * lw.y + lb.y, 0.f);
            ag2 += fmaxf((y.z - mu) * rstd * lw.z + lb.z, 0.f);
            ag3 += fmaxf((y.w - mu) * rstd * lw.w + lb.w, 0.f);
        }
        *(float4*)&Ps[warp * 128 + lane * 4] = make_float4(ag0, ag1, ag2, ag3);
    }
    __syncthreads();
    {
        int bi_l = tid >> 7, f = tid & 127;
        g_agg[(bi0 + bi_l) * 128 + f] =
            Ps[(4 * bi_l) * 128 + f] + Ps[(4 * bi_l + 1) * 128 + f] +
            Ps[(4 * bi_l + 2) * 128 + f] + Ps[(4 * bi_l + 3) * 128 + f];
    }
}

// ---------------- fused object update (+rs or +predict): 16 nodes/block, 512 thr, k-split ----------------
__global__ __launch_bounds__(512) void obj_update_f(const float* __restrict__ pp_w,
                                                    const float* __restrict__ pp_b,
                                                    const float* __restrict__ pp_lnw,
                                                    const float* __restrict__ pp_lnb,
                                                    const float* __restrict__ rp_w,
                                                    const float* __restrict__ rp_b,
                                                    const float* __restrict__ pr_w0,
                                                    const float* __restrict__ pr_b0,
                                                    const float* __restrict__ pr_w1,
                                                    const float* __restrict__ pr_b1,
                                                    float* __restrict__ out,
                                                    int mode) {  // 0: +rs, 1: +predict
    extern __shared__ float sm[];
    float* Xs   = sm;            // [16][256]
    float* part = sm + 4096;     // 8192
    float* Cs   = sm + 12288;    // [16][128]
    float* Os2  = sm + 14336;    // [16][128]
    float* Hs2  = sm + 16384;    // [16][128]
    int base = blockIdx.x * 16;
    int tid = threadIdx.x;
    int warp = tid >> 5, lane = tid & 31;

#pragma unroll
    for (int i = 0; i < 8; i++) {
        int idx = i * 512 + tid;
        int n = idx >> 8, c = idx & 255;
        Xs[idx] = (c < 128) ? g_obj[(base + n) * 128 + c]
                            : g_agg[(base + n) * 128 + (c - 128)];
    }
    __syncthreads();

    {
        int f = tid & 127, q = tid >> 7;
        float acc[16];
#pragma unroll
        for (int n = 0; n < 16; n++) acc[n] = 0.f;
        const float* wrow = pp_w + f * 256 + q * 64;
        const float* xb = Xs + q * 64;
#pragma unroll 4
        for (int k = 0; k < 64; k += 4) {
            float4 w = *(const float4*)&wrow[k];
#pragma unroll
            for (int n = 0; n < 16; n++) {
                float4 x = *(const float4*)&xb[n * 256 + k];
                acc[n] += w.x * x.x + w.y * x.y + w.z * x.z + w.w * x.w;
            }
        }
#pragma unroll
        for (int n = 0; n < 16; n++) part[q * 2048 + n * 128 + f] = acc[n];
    }
    __syncthreads();
#pragma unroll
    for (int i = 0; i < 4; i++) {
        int idx = i * 512 + tid;
        float v = part[idx] + part[2048 + idx] + part[4096 + idx] + part[6144 + idx];
        Cs[idx] = v + pp_b[idx & 127];
    }
    __syncthreads();

    {
        float4 lw = *(const float4*)&pp_lnw[lane * 4];
        float4 lb = *(const float4*)&pp_lnb[lane * 4];
        int n = warp;
        float4 y = *(const float4*)&Cs[n * 128 + lane * 4];
        float s = y.x + y.y + y.z + y.w;
        float ss = y.x * y.x + y.y * y.y + y.z * y.z + y.w * y.w;
#pragma unroll
        for (int off = 16; off; off >>= 1) {
            s += __shfl_xor_sync(0xffffffffu, s, off);
            ss += __shfl_xor_sync(0xffffffffu, ss, off);
        }
        float mu = s * 0.0078125f;
        float var = ss * 0.0078125f - mu * mu;
        float rstd = rsqrtf(var + 1e-5f);
        float4 o = make_float4(fmaxf((y.x - mu) * rstd * lw.x + lb.x, 0.f),
                               fmaxf((y.y - mu) * rstd * lw.y + lb.y, 0.f),
                               fmaxf((y.z - mu) * rstd * lw.z + lb.z, 0.f),
                               fmaxf((y.w - mu) * rstd * lw.w + lb.w, 0.f));
        *(float4*)&Os2[n * 128 + lane * 4] = o;
        if (mode == 0) *(float4*)&g_obj[(base + n) * 128 + lane * 4] = o;
    }
    __syncthreads();

    if (mode == 0) {
        int fo = tid & 255, q = tid >> 8;
        float acc[16];
#pragma unroll
        for (int n = 0; n < 16; n++) acc[n] = 0.f;
        const float* wrow = (fo < 128) ? (rp_w + fo * 384 + 128 + q * 64)
                                       : (rp_w + (fo - 128) * 384 + 256 + q * 64);
        const float* ob = Os2 + q * 64;
#pragma unroll 4
        for (int k = 0; k < 64; k += 4) {
            float4 w = *(const float4*)&wrow[k];
#pragma unroll
            for (int n = 0; n < 16; n++) {
                float4 x = *(const float4*)&ob[n * 128 + k];
                acc[n] += w.x * x.x + w.y * x.y + w.z * x.z + w.w * x.w;
            }
        }
#pragma unroll
        for (int n = 0; n < 16; n++) part[q * 4096 + n * 256 + fo] = acc[n];
        __syncthreads();
#pragma unroll
        for (int i = 0; i < 8; i++) {
            int idx = i * 512 + tid;
            float v = part[idx] + part[4096 + idx];
            int n = idx >> 8, fo2 = idx & 255;
            if (fo2 < 128) g_R[(base + n) * 128 + fo2] = v + rp_b[fo2];
            else g_S[(base + n) * 128 + fo2 - 128] = v;
        }
    } else {
        {
            int f = tid & 127, q = tid >> 7;
            float acc[16];
#pragma unroll
            for (int n = 0; n < 16; n++) acc[n] = 0.f;
            const float* wrow = pr_w0 + f * 128 + q * 32;
            const float* ob = Os2 + q * 32;
#pragma unroll 4
            for (int k = 0; k < 32; k += 4) {
                float4 w = *(const float4*)&wrow[k];
#pragma unroll
                for (int n = 0; n < 16; n++) {
                    float4 x = *(const float4*)&ob[n * 128 + k];
                    acc[n] += w.x * x.x + w.y * x.y + w.z * x.z + w.w * x.w;
                }
            }
#pragma unroll
            for (int n = 0; n < 16; n++) part[q * 2048 + n * 128 + f] = acc[n];
        }
        __syncthreads();
#pragma unroll
        for (int i = 0; i < 4; i++) {
            int idx = i * 512 + tid;
            float v = part[idx] + part[2048 + idx] + part[4096 + idx] + part[6144 + idx];
            Hs2[idx] = fmaxf(v + pr_b0[idx & 127], 0.f);
        }
        __syncthreads();
        {
            int n = tid >> 5, op = tid & 31;
            float a0 = 0.f;
            const float* wp = pr_w1 + op * 128;
#pragma unroll 4
            for (int k = 0; k < 128; k += 4) {
                float4 x = *(const float4*)&Hs2[n * 128 + k];
                float4 w = *(const float4*)&wp[k];
                a0 += w.x * x.x + w.y * x.y + w.z * x.z + w.w * x.w;
            }
            out[(base + n) * 32 + op] = tanhf(a0 + pr_b1[op]);
        }
    }
}

// ---------------- launch ----------------
extern "C" void kernel_launch(void* const* d_in, const int* in_sizes, int n_in,
                              void* d_out, int out_size) {
    const float* attrs     = (const float*)d_in[0];
    const float* states    = (const float*)d_in[1];
    const float* rel_attrs = (const float*)d_in[3];
    const float* oe_w0 = (const float*)d_in[4];
    const float* oe_b0 = (const float*)d_in[5];
    const float* oe_w1 = (const float*)d_in[6];
    const float* oe_b1 = (const float*)d_in[7];
    const float* re_w0 = (const float*)d_in[8];
    const float* re_b0 = (const float*)d_in[9];
    const float* re_w1 = (const float*)d_in[10];
    const float* re_b1 = (const float*)d_in[11];
    const float* rp_w  = (const float*)d_in[12];
    const float* rp_b  = (const float*)d_in[13];
    const float* rp_lnw = (const float*)d_in[14];
    const float* rp_lnb = (const float*)d_in[15];
    const float* pp_w  = (const float*)d_in[16];
    const float* pp_b  = (const float*)d_in[17];
    const float* pp_lnw = (const float*)d_in[18];
    const float* pp_lnb = (const float*)d_in[19];
    const float* pr_w0 = (const float*)d_in[20];
    const float* pr_b0 = (const float*)d_in[21];
    const float* pr_w1 = (const float*)d_in[22];
    const float* pr_b1 = (const float*)d_in[23];
    float* out = (float*)d_out;

    const int dsm_bytes = 44160 * 4;   // ~172.5 KB
    const int ou_bytes  = 18432 * 4;   // 72 KB
    cudaFuncSetAttribute(rel_fused_h, cudaFuncAttributeMaxDynamicSharedMemorySize, dsm_bytes);
    cudaFuncSetAttribute(obj_update_f, cudaFuncAttributeMaxDynamicSharedMemorySize, ou_bytes);

    encode_all<<<256, 128>>>(attrs, states, re_w0, re_b0, oe_w0, oe_b0, oe_w1, oe_b1,
                             re_w1, rp_w, rp_b);
    rel_fused_h<<<512, 512, dsm_bytes>>>(rel_attrs, re_w0, re_b1, rp_lnw, rp_lnb);
    obj_update_f<<<128, 512, ou_bytes>>>(pp_w, pp_b, pp_lnw, pp_lnb, rp_w, rp_b,
                                         pr_w0, pr_b0, pr_w1, pr_b1, out, 0);
    edge_apply_v2<<<512, 512>>>(rp_lnw, rp_lnb);
    obj_update_f<<<128, 512, ou_bytes>>>(pp_w, pp_b, pp_lnw, pp_lnb, rp_w, rp_b,
                                         pr_w0, pr_b0, pr_w1, pr_b1, out, 1);
}